// round 10
// baseline (speedup 1.0000x reference)
#include <cuda_runtime.h>

#define BSZ 512
#define DIM 65536
#define NT 1024
#define TILE 16384
#define SMEM_BYTES (TILE * 8)

struct Gate { short type; unsigned short m0; unsigned short m1; short ang; };
// type: 0=RX, 1=RY, 2=CNOT(m0=target mask, m1=control mask); ang indexes g_trig.

__device__ float2 g_psi[(long long)BSZ * DIM];
__device__ float  g_norminv[BSZ];
__device__ float2 g_trig[24];
__device__ float  g_part[BSZ * 4 * 32];

// Tile A local mask for wire w (w=2..15): 1<<(15-w).
// Tile B local mask: w in {6..15}: 1<<(15-w); w in {0..3}: 1<<(13-w).
__constant__ Gate cP1[17] = {
  {1,1024,0,1},{2,16,32,0},{0,1,0,3},{1,2048,0,4},{2,32,64,0},{0,2,0,6},
  {1,4096,0,7},{2,64,128,0},{0,4,0,9},{1,8192,0,10},{2,128,256,0},{0,8,0,12},
  {2,256,512,0},{0,16,0,15},{2,512,1024,0},{0,32,0,18},{1,1,0,19}
};
__constant__ Gate cP2[20] = {
  {0,8192,0,0},{1,4096,0,13},{1,8192,0,16},
  {0,8192,0,20},{0,4096,0,20},{0,2048,0,20},{0,1024,0,20},
  {0,512,0,20},{0,256,0,20},{0,128,0,20},{0,64,0,20},{0,32,0,20},{0,16,0,20},
  {0,8,0,20},{0,4,0,20},{0,2,0,20},{0,1,0,20},
  {2,4096,8192,0},{2,2048,4096,0},{2,1024,2048,0}
};
__constant__ Gate cP3[27] = {
  {0,2048,0,20},{0,1024,0,20},
  {2,2048,4096,0},{2,1024,2048,0},{2,512,1024,0},{2,256,512,0},{2,128,256,0},{2,64,128,0},
  {2,32,64,0},{2,16,32,0},{2,8,16,0},{2,4,8,0},{2,2,4,0},{2,1,2,0},
  {1,8192,0,22},{1,4096,0,22},{1,2048,0,22},{1,1024,0,22},{1,512,0,22},{1,256,0,22},
  {1,128,0,22},{1,64,0,22},{1,32,0,22},{1,16,0,22},{1,8,0,22},{1,4,0,22},{1,2,0,22}
};
__constant__ Gate cP4[21] = {
  {2,8192,1,0},{1,1,0,22},{1,8192,0,22},{1,4096,0,22},
  {0,8192,0,21},{0,4096,0,21},{0,2048,0,21},{0,1024,0,21},
  {0,512,0,21},{0,256,0,21},{0,128,0,21},{0,64,0,21},{0,32,0,21},{0,16,0,21},
  {0,8,0,21},{0,4,0,21},{0,2,0,21},{0,1,0,21},
  {2,4096,8192,0},{2,2048,4096,0},{2,1024,2048,0}
};
__constant__ Gate cP5[14] = {
  {0,2048,0,21},{0,1024,0,21},
  {2,2048,4096,0},{2,1024,2048,0},{2,512,1024,0},{2,256,512,0},{2,128,256,0},{2,64,128,0},
  {2,32,64,0},{2,16,32,0},{2,8,16,0},{2,4,8,0},{2,2,4,0},{2,1,2,0}
};
// attn_0 = <Z15 Z0>, attn_w = <Z_w>; m_w = cos*attn_w - sin*<Xop_w>,
// Xop_0 = X_b15, Xop_15 = X_b15 X_b0, Xop_1 = X_b14, else in-tile X.

// Grouped sweep engine: up to 4 consecutive rotations on DISTINCT wires per sweep.
// (Rotations on distinct wires commute -> ascending-mask sort is legal. Gates on
// the same wire never enter one group, preserving their original order.)
__device__ __forceinline__ void apply_gates(float2* t, const Gate* gs, int n) {
  int g = 0;
  while (g < n) {
    __syncthreads();
    if (gs[g].type == 2) {
      const int mT = gs[g].m0, mC = gs[g].m1;
      const int lo = (mT < mC) ? mT : mC;
      const int hi = mT ^ mC ^ lo;
      for (int q = threadIdx.x; q < TILE / 4; q += NT) {
        int i = ((q & ~(lo - 1)) << 1) | (q & (lo - 1));
        i = ((i & ~(hi - 1)) << 1) | (i & (hi - 1));
        i |= mC;
        float2 a = t[i], b = t[i | mT];
        t[i] = b; t[i | mT] = a;
      }
      g++;
    } else {
      int m[4]; int ty[4]; float cc[4], ss[4];
      int G = 0;
      while (G < 4 && g + G < n && gs[g + G].type != 2) {
        int cand = gs[g + G].m0;
        bool dup = false;
        for (int k = 0; k < G; k++) if (m[k] == cand) dup = true;
        if (dup) break;                       // same wire again -> close group
        m[G] = cand; ty[G] = gs[g + G].type;
        float2 cs = g_trig[gs[g + G].ang]; cc[G] = cs.x; ss[G] = cs.y;
        G++;
      }
      for (int i = 1; i < G; i++)             // sort by mask (distinct wires commute)
        for (int j = i; j > 0 && m[j] < m[j - 1]; j--) {
          int tm = m[j]; m[j] = m[j - 1]; m[j - 1] = tm;
          int tt = ty[j]; ty[j] = ty[j - 1]; ty[j - 1] = tt;
          float tc = cc[j]; cc[j] = cc[j - 1]; cc[j - 1] = tc;
          float ts = ss[j]; ss[j] = ss[j - 1]; ss[j - 1] = ts;
        }
      const int namps = 1 << G;
      for (int q = threadIdx.x; q < (TILE >> G); q += NT) {
        int idx = q;
        for (int k = 0; k < G; k++)
          idx = ((idx & ~(m[k] - 1)) << 1) | (idx & (m[k] - 1));
        float2 v[16];
#pragma unroll
        for (int j = 0; j < 16; j++) if (j < namps) {
          int off = 0;
#pragma unroll
          for (int k = 0; k < 4; k++) if (k < G && ((j >> k) & 1)) off |= m[k];
          v[j] = t[idx | off];
        }
#pragma unroll
        for (int k = 0; k < 4; k++) if (k < G) {
          const float c = cc[k], s = ss[k];
          if (ty[k] == 0) {
#pragma unroll
            for (int j = 0; j < 16; j++) if (j < namps && !((j >> k) & 1)) {
              float2 a = v[j], b = v[j | (1 << k)];
              v[j]            = make_float2(c * a.x + s * b.y,  c * a.y - s * b.x);
              v[j | (1 << k)] = make_float2(s * a.y + c * b.x, -s * a.x + c * b.y);
            }
          } else {
#pragma unroll
            for (int j = 0; j < 16; j++) if (j < namps && !((j >> k) & 1)) {
              float2 a = v[j], b = v[j | (1 << k)];
              v[j]            = make_float2(c * a.x - s * b.x, c * a.y - s * b.y);
              v[j | (1 << k)] = make_float2(s * a.x + c * b.x, s * a.y + c * b.y);
            }
          }
        }
#pragma unroll
        for (int j = 0; j < 16; j++) if (j < namps) {
          int off = 0;
#pragma unroll
          for (int k = 0; k < 4; k++) if (k < G && ((j >> k) & 1)) off |= m[k];
          t[idx | off] = v[j];
        }
      }
      g += G;
    }
  }
  __syncthreads();
}

__device__ __forceinline__ void loadA(float2* t, int b, int o) {
  const float4* gp = (const float4*)(g_psi + (long long)b * DIM + o * TILE);
  float4* sp = (float4*)t;
  for (int k = threadIdx.x; k < TILE / 2; k += NT) sp[k] = gp[k];
}
__device__ __forceinline__ void storeA(const float2* t, int b, int o) {
  float4* gp = (float4*)(g_psi + (long long)b * DIM + o * TILE);
  const float4* sp = (const float4*)t;
  for (int k = threadIdx.x; k < TILE / 2; k += NT) gp[k] = sp[k];
}
__device__ __forceinline__ void loadB(float2* t, int b, int o) {
  const float2* base = g_psi + (long long)b * DIM + (o << 10);
  float4* sp = (float4*)t;
  for (int k = threadIdx.x; k < TILE / 2; k += NT) {
    int l = k << 1;
    int r = l >> 10, lo = l & 1023;
    sp[k] = *(const float4*)(base + ((long long)r << 12) + lo);
  }
}
__device__ __forceinline__ void storeB(const float2* t, int b, int o) {
  float2* base = g_psi + (long long)b * DIM + (o << 10);
  const float4* sp = (const float4*)t;
  for (int k = threadIdx.x; k < TILE / 2; k += NT) {
    int l = k << 1;
    int r = l >> 10, lo = l & 1023;
    *(float4*)(base + ((long long)r << 12) + lo) = sp[k];
  }
}

__global__ void kTrig(const float* ra, const float* trx, const float* try_) {
  int i = threadIdx.x;
  float a;
  if (i < 20) a = ra[i];
  else if (i < 22) a = trx[i - 20];
  else if (i < 24) a = try_[i - 22];
  else return;
  g_trig[i] = make_float2(cosf(a * 0.5f), sinf(a * 0.5f));
}

__global__ void __launch_bounds__(256) kNorm(const float* states) {
  __shared__ float red[256];
  int b = blockIdx.x;
  const float4* p = (const float4*)(states + (long long)b * DIM);
  float s = 0.f;
  for (int k = threadIdx.x; k < DIM / 4; k += 256) {
    float4 v = p[k];
    s += v.x * v.x + v.y * v.y + v.z * v.z + v.w * v.w;
  }
  red[threadIdx.x] = s;
  __syncthreads();
  for (int off = 128; off; off >>= 1) {
    if (threadIdx.x < off) red[threadIdx.x] += red[threadIdx.x + off];
    __syncthreads();
  }
  if (threadIdx.x == 0) g_norminv[b] = rsqrtf(red[0]);
}

__global__ void __launch_bounds__(NT) kP1(const float* states) {
  extern __shared__ float2 t[];
  int b = blockIdx.x >> 2, o = blockIdx.x & 3;
  float ninv = g_norminv[b];
  const float4* gp = (const float4*)(states + (long long)b * DIM + o * TILE);
  for (int k = threadIdx.x; k < TILE / 4; k += NT) {
    float4 v = gp[k];
    t[4 * k + 0] = make_float2(v.x * ninv, 0.f);
    t[4 * k + 1] = make_float2(v.y * ninv, 0.f);
    t[4 * k + 2] = make_float2(v.z * ninv, 0.f);
    t[4 * k + 3] = make_float2(v.w * ninv, 0.f);
  }
  apply_gates(t, cP1, 17);
  storeA(t, b, o);
}
__global__ void __launch_bounds__(NT) kP2() {
  extern __shared__ float2 t[];
  int b = blockIdx.x >> 2, o = blockIdx.x & 3;
  loadB(t, b, o); apply_gates(t, cP2, 20); storeB(t, b, o);
}
__global__ void __launch_bounds__(NT) kP3() {
  extern __shared__ float2 t[];
  int b = blockIdx.x >> 2, o = blockIdx.x & 3;
  loadA(t, b, o); apply_gates(t, cP3, 27); storeA(t, b, o);
}
__global__ void __launch_bounds__(NT) kP4() {
  extern __shared__ float2 t[];
  int b = blockIdx.x >> 2, o = blockIdx.x & 3;
  loadB(t, b, o); apply_gates(t, cP4, 21); storeB(t, b, o);
}
__global__ void __launch_bounds__(NT) kP5() {
  extern __shared__ float2 t[];
  int b = blockIdx.x >> 2, o = blockIdx.x & 3;
  loadA(t, b, o); apply_gates(t, cP5, 14); storeA(t, b, o);
}

__global__ void __launch_bounds__(NT) kMeasure() {
  extern __shared__ float2 t[];
  int b = blockIdx.x >> 2, o = blockIdx.x & 3;
  loadA(t, b, o);
  __syncthreads();

  float zacc[16], xacc[16];
#pragma unroll
  for (int w = 0; w < 16; ++w) { zacc[w] = 0.f; xacc[w] = 0.f; }

  for (int l = threadIdx.x; l < TILE; l += NT) {
    float2 a = t[l];
    float p = a.x * a.x + a.y * a.y;
    int i = (o << 14) | l;
    zacc[0] += (((i >> 15) ^ i) & 1) ? -p : p;
#pragma unroll
    for (int w = 1; w < 16; ++w)
      zacc[w] += ((i >> (15 - w)) & 1) ? -p : p;
  }

#pragma unroll
  for (int w = 2; w <= 14; ++w) {
    const int m = 1 << (15 - w);
    float acc = 0.f;
    for (int q = threadIdx.x; q < TILE / 2; q += NT) {
      int i0 = ((q & ~(m - 1)) << 1) | (q & (m - 1));
      float2 a = t[i0], bb = t[i0 | m];
      acc += a.x * bb.x + a.y * bb.y;
    }
    xacc[w] = 2.f * acc;
  }

  const float2* base = g_psi + (long long)b * DIM;
  if (o < 2) {
    float a0 = 0.f, a15 = 0.f;
    for (int l = threadIdx.x; l < TILE; l += NT) {
      int i = (o << 14) | l;
      float2 a = t[l];
      float2 p0 = base[i | 0x8000];
      float2 p1 = base[(i | 0x8000) ^ 1];
      a0 += a.x * p0.x + a.y * p0.y;
      a15 += a.x * p1.x + a.y * p1.y;
    }
    xacc[0] = 2.f * a0;
    xacc[15] = 2.f * a15;
  }
  if ((o & 1) == 0) {
    float a1 = 0.f;
    for (int l = threadIdx.x; l < TILE; l += NT) {
      int i = (o << 14) | l;
      float2 a = t[l];
      float2 p = base[i | 0x4000];
      a1 += a.x * p.x + a.y * p.y;
    }
    xacc[1] = 2.f * a1;
  }

  __syncthreads();
  float* red = (float*)t;
  int lane = threadIdx.x & 31, wid = threadIdx.x >> 5;
#pragma unroll
  for (int v = 0; v < 32; ++v) {
    float val = (v < 16) ? zacc[v] : xacc[v - 16];
#pragma unroll
    for (int off = 16; off; off >>= 1) val += __shfl_down_sync(0xffffffffu, val, off);
    if (lane == 0) red[wid * 32 + v] = val;
  }
  __syncthreads();
  if (threadIdx.x < 32) {
    int v = threadIdx.x;
    float s = 0.f;
    for (int w = 0; w < NT / 32; ++w) s += red[w * 32 + v];
    g_part[blockIdx.x * 32 + v] = s;
  }
}

__global__ void __launch_bounds__(128) kHead(
    const float* theta_ry, const float* w1, const float* b1,
    const float* w2, const float* b2, const float* g1, const float* be1,
    const float* g2, const float* be2, const float* wh, const float* bh,
    float* out) {
  int b = blockIdx.x * blockDim.x + threadIdx.x;
  if (b >= BSZ) return;

  float attn[16], xs[16];
#pragma unroll
  for (int w = 0; w < 16; ++w) {
    float za = 0.f, xa = 0.f;
#pragma unroll
    for (int o = 0; o < 4; ++o) {
      za += g_part[(b * 4 + o) * 32 + w];
      xa += g_part[(b * 4 + o) * 32 + 16 + w];
    }
    attn[w] = za; xs[w] = xa;
  }
  float th = theta_ry[1];
  float cb = cosf(th), sb = sinf(th);
  float m[16];
#pragma unroll
  for (int w = 0; w < 16; ++w) m[w] = cb * attn[w] - sb * xs[w];

  float mu = 0.f;
#pragma unroll
  for (int w = 0; w < 16; ++w) mu += attn[w];
  mu *= (1.f / 16.f);
  float var = 0.f;
#pragma unroll
  for (int w = 0; w < 16; ++w) { float d = attn[w] - mu; var += d * d; }
  var *= (1.f / 16.f);
  float rs = rsqrtf(var + 1e-5f);
  float x[16];
#pragma unroll
  for (int w = 0; w < 16; ++w) x[w] = (attn[w] - mu) * rs * g1[16 + w] + be1[16 + w];

  float ffn[16];
#pragma unroll
  for (int w = 0; w < 16; ++w) ffn[w] = b2[16 + w];
  for (int j = 0; j < 64; ++j) {
    float h = b1[64 + j];
#pragma unroll
    for (int w = 0; w < 16; ++w) h += m[w] * w1[1024 + j * 16 + w];
    h = fmaxf(h, 0.f);
#pragma unroll
    for (int w = 0; w < 16; ++w) ffn[w] += h * w2[1024 + w * 64 + j];
  }

  float y[16];
#pragma unroll
  for (int w = 0; w < 16; ++w) y[w] = x[w] + ffn[w];
  float mu2 = 0.f;
#pragma unroll
  for (int w = 0; w < 16; ++w) mu2 += y[w];
  mu2 *= (1.f / 16.f);
  float var2 = 0.f;
#pragma unroll
  for (int w = 0; w < 16; ++w) { float d = y[w] - mu2; var2 += d * d; }
  var2 *= (1.f / 16.f);
  float rs2 = rsqrtf(var2 + 1e-5f);

  float ov = bh[0];
#pragma unroll
  for (int w = 0; w < 16; ++w)
    ov += ((y[w] - mu2) * rs2 * g2[16 + w] + be2[16 + w]) * wh[w];
  out[b] = ov;
}

extern "C" void kernel_launch(void* const* d_in, const int* in_sizes, int n_in,
                              void* d_out, int out_size) {
  const float* states = (const float*)d_in[0];
  const float* ra     = (const float*)d_in[1];
  const float* trx    = (const float*)d_in[2];
  const float* try_   = (const float*)d_in[3];
  const float* w1     = (const float*)d_in[4];
  const float* b1     = (const float*)d_in[5];
  const float* w2     = (const float*)d_in[6];
  const float* b2     = (const float*)d_in[7];
  const float* g1     = (const float*)d_in[8];
  const float* be1    = (const float*)d_in[9];
  const float* g2     = (const float*)d_in[10];
  const float* be2    = (const float*)d_in[11];
  const float* wh     = (const float*)d_in[12];
  const float* bh     = (const float*)d_in[13];
  float* out = (float*)d_out;

  cudaFuncSetAttribute(kP1, cudaFuncAttributeMaxDynamicSharedMemorySize, SMEM_BYTES);
  cudaFuncSetAttribute(kP2, cudaFuncAttributeMaxDynamicSharedMemorySize, SMEM_BYTES);
  cudaFuncSetAttribute(kP3, cudaFuncAttributeMaxDynamicSharedMemorySize, SMEM_BYTES);
  cudaFuncSetAttribute(kP4, cudaFuncAttributeMaxDynamicSharedMemorySize, SMEM_BYTES);
  cudaFuncSetAttribute(kP5, cudaFuncAttributeMaxDynamicSharedMemorySize, SMEM_BYTES);
  cudaFuncSetAttribute(kMeasure, cudaFuncAttributeMaxDynamicSharedMemorySize, SMEM_BYTES);

  kTrig<<<1, 32>>>(ra, trx, try_);
  kNorm<<<BSZ, 256>>>(states);
  kP1<<<BSZ * 4, NT, SMEM_BYTES>>>(states);
  kP2<<<BSZ * 4, NT, SMEM_BYTES>>>();
  kP3<<<BSZ * 4, NT, SMEM_BYTES>>>();
  kP4<<<BSZ * 4, NT, SMEM_BYTES>>>();
  kP5<<<BSZ * 4, NT, SMEM_BYTES>>>();
  kMeasure<<<BSZ * 4, NT, SMEM_BYTES>>>();
  kHead<<<(BSZ + 127) / 128, 128>>>(try_, w1, b1, w2, b2, g1, be1, g2, be2, wh, bh, out);
}

// round 11
// speedup vs baseline: 1.7700x; 1.7700x over previous
#include <cuda_runtime.h>

#define BSZ 512
#define DIM 65536
#define NT 512
#define TILE 16384
#define SMEM_BYTES (TILE * 8)

__device__ float2 g_psi[(long long)BSZ * DIM];   // 256 MB scratch statevector
__device__ float  g_norminv[BSZ];
__device__ float2 g_Umat[56][4];                 // per-wire composite 2x2 unitaries
__device__ float  g_part[BSZ * 4 * 32];

__device__ __forceinline__ int sw(int l) { return l ^ ((l >> 4) & 15); }

// ---- 2x2 complex helpers (setup only) ----
struct C2 { float2 a, b, c, d; };
__device__ __forceinline__ float2 cmul(float2 x, float2 y) {
  return make_float2(x.x * y.x - x.y * y.y, x.x * y.y + x.y * y.x);
}
__device__ __forceinline__ float2 cad(float2 x, float2 y) { return make_float2(x.x + y.x, x.y + y.y); }
__device__ C2 mmul(C2 X, C2 Y) {   // X*Y (Y applied first)
  C2 r;
  r.a = cad(cmul(X.a, Y.a), cmul(X.b, Y.c));
  r.b = cad(cmul(X.a, Y.b), cmul(X.b, Y.d));
  r.c = cad(cmul(X.c, Y.a), cmul(X.d, Y.c));
  r.d = cad(cmul(X.c, Y.b), cmul(X.d, Y.d));
  return r;
}

// Setup: trig + composite unitary table.
// Slots: P1pre b0..b3:0-3, b10..b13:4-7; P1post b4,b5:8-9
//        P2 b0..b11:10-21, b12:22, b13:23
//        P3 b10,b11:24-25; b1..b13 (RY):26-38
//        P4 b1..b11:39-49, b12:50, b0:51, b13:52;  P5 b10,b11:53-54
__global__ void kSetup(const float* ra, const float* trx, const float* try_) {
  if (threadIdx.x) return;
  float2 tg[24];
  for (int i = 0; i < 24; i++) {
    float a = (i < 20) ? ra[i] : (i < 22 ? trx[i - 20] : try_[i - 22]);
    tg[i] = make_float2(cosf(a * 0.5f), sinf(a * 0.5f));
  }
#define MRX(i) C2{make_float2(tg[i].x,0.f), make_float2(0.f,-tg[i].y), make_float2(0.f,-tg[i].y), make_float2(tg[i].x,0.f)}
#define MRY(i) C2{make_float2(tg[i].x,0.f), make_float2(-tg[i].y,0.f), make_float2(tg[i].y,0.f), make_float2(tg[i].x,0.f)}
  C2 M[56];
  M[0] = mmul(MRY(19), MRX(3));
  M[1] = MRX(6);  M[2] = MRX(9);  M[3] = MRX(12);
  M[4] = MRY(1);  M[5] = MRY(4);  M[6] = MRY(7);  M[7] = MRY(10);
  M[8] = MRX(15); M[9] = MRX(18);
  for (int k = 10; k <= 21; k++) M[k] = MRX(20);
  M[22] = mmul(MRX(20), MRY(13));
  M[23] = mmul(MRX(20), mmul(MRY(16), MRX(0)));
  M[24] = MRX(20); M[25] = MRX(20);
  for (int k = 26; k <= 38; k++) M[k] = MRY(22);
  for (int k = 39; k <= 49; k++) M[k] = MRX(21);
  M[50] = mmul(MRX(21), MRY(22));
  M[51] = M[50]; M[52] = M[50];
  M[53] = MRX(21); M[54] = MRX(21);
  for (int k = 0; k < 55; k++) {
    g_Umat[k][0] = M[k].a; g_Umat[k][1] = M[k].b;
    g_Umat[k][2] = M[k].c; g_Umat[k][3] = M[k].d;
  }
}

// ---- static sweep: apply NW general unitaries on compile-time masks (ascending) ----
template<int NW, int M0, int M1, int M2, int M3>
__device__ __forceinline__ void usweep(float2* t, int ubase) {
  constexpr int NA = 1 << NW;
  constexpr int ITERS = (TILE >> NW) / NT;
  float2 U[NW][4];
#pragma unroll
  for (int k = 0; k < NW; k++)
#pragma unroll
    for (int e = 0; e < 4; e++) U[k][e] = g_Umat[ubase + k][e];
  __syncthreads();
#pragma unroll
  for (int it = 0; it < ITERS; it++) {
    int q = threadIdx.x + it * NT;
    int idx = q;
    idx = ((idx & ~(M0 - 1)) << 1) | (idx & (M0 - 1));
    if (NW > 1) idx = ((idx & ~(M1 - 1)) << 1) | (idx & (M1 - 1));
    if (NW > 2) idx = ((idx & ~(M2 - 1)) << 1) | (idx & (M2 - 1));
    if (NW > 3) idx = ((idx & ~(M3 - 1)) << 1) | (idx & (M3 - 1));
    const int MS[4] = {M0, M1, M2, M3};
    float2 v[NA];
#pragma unroll
    for (int j = 0; j < NA; j++) {
      int off = 0;
#pragma unroll
      for (int k = 0; k < NW; k++) if ((j >> k) & 1) off |= MS[k];
      v[j] = t[sw(idx | off)];
    }
#pragma unroll
    for (int k = 0; k < NW; k++) {
      const float2 u00 = U[k][0], u01 = U[k][1], u10 = U[k][2], u11 = U[k][3];
#pragma unroll
      for (int j = 0; j < NA; j++) if (!((j >> k) & 1)) {
        float2 a = v[j], b = v[j | (1 << k)];
        v[j] = make_float2(
          u00.x * a.x - u00.y * a.y + u01.x * b.x - u01.y * b.y,
          u00.x * a.y + u00.y * a.x + u01.x * b.y + u01.y * b.x);
        v[j | (1 << k)] = make_float2(
          u10.x * a.x - u10.y * a.y + u11.x * b.x - u11.y * b.y,
          u10.x * a.y + u10.y * a.x + u11.x * b.y + u11.y * b.x);
      }
    }
#pragma unroll
    for (int j = 0; j < NA; j++) {
      int off = 0;
#pragma unroll
      for (int k = 0; k < NW; k++) if ((j >> k) & 1) off |= MS[k];
      t[sw(idx | off)] = v[j];
    }
  }
}

// CNOT-chain permutation sweep. ASC: P1's ascending chain (targets b4..b9,
// controls b5..b10). Else: 12-CNOT descending ladder src = d ^ ((d>>1)&0xFFF).
template<bool ASC>
__device__ __forceinline__ void permchain(float2* t) {
  __syncthreads();
  constexpr int PER = TILE / NT;   // 32
  float2 v[PER];
  int d0 = threadIdx.x * PER;
#pragma unroll
  for (int j = 0; j < PER; j++) {
    int d = d0 + j, src;
    if (ASC) {
      src = d;
#pragma unroll
      for (int k = 9; k >= 4; k--) src ^= (src >> 1) & (1 << k);
    } else {
      src = d ^ ((d >> 1) & 0x0FFF);
    }
    v[j] = t[sw(src)];
  }
  __syncthreads();
#pragma unroll
  for (int j = 0; j < PER; j++) t[sw(d0 + j)] = v[j];
}

// ---- global <-> smem tile movement (smem swizzled) ----
__device__ __forceinline__ void loadA(float2* t, int b, int o) {
  const float4* gp = (const float4*)(g_psi + (long long)b * DIM + o * TILE);
  for (int k = threadIdx.x; k < TILE / 2; k += NT) {
    float4 w4 = gp[k];
    t[sw(2 * k)]     = make_float2(w4.x, w4.y);
    t[sw(2 * k + 1)] = make_float2(w4.z, w4.w);
  }
}
__device__ __forceinline__ void storeA(const float2* t, int b, int o) {
  float4* gp = (float4*)(g_psi + (long long)b * DIM + o * TILE);
  for (int k = threadIdx.x; k < TILE / 2; k += NT) {
    float2 a = t[sw(2 * k)], c = t[sw(2 * k + 1)];
    gp[k] = make_float4(a.x, a.y, c.x, c.y);
  }
}
// Tile B: local [13:10] -> global [15:12]; o -> [11:10]; local [9:0] -> [9:0].
// lead=1 folds the leading CNOT (t=b13, c=b0) into the load.
__device__ __forceinline__ void loadB(float2* t, int b, int o, int lead) {
  const float2* base = g_psi + (long long)b * DIM + (o << 10);
  for (int k = threadIdx.x; k < TILE / 2; k += NT) {
    int s = 2 * k;
    int r = s >> 10, lo = s & 1023;
    float4 w4 = *(const float4*)(base + (r << 12) + lo);
    t[sw(s)] = make_float2(w4.x, w4.y);
    int d1 = (s + 1) ^ (lead << 13);
    t[sw(d1)] = make_float2(w4.z, w4.w);
  }
}
// foldmask folds trailing CNOT chain: final[l] = t[l ^ ((l>>1)&foldmask)].
__device__ __forceinline__ void storeB(const float2* t, int b, int o, int foldmask) {
  float2* base = g_psi + (long long)b * DIM + (o << 10);
  for (int k = threadIdx.x; k < TILE / 2; k += NT) {
    int d = 2 * k;
    int src = d ^ ((d >> 1) & foldmask);
    float2 a = t[sw(src)], c = t[sw(src + 1)];
    int r = d >> 10, lo = d & 1023;
    *(float4*)(base + (r << 12) + lo) = make_float4(a.x, a.y, c.x, c.y);
  }
}

// ---- kernels ----
__global__ void __launch_bounds__(256) kNorm(const float* states) {
  __shared__ float red[256];
  int b = blockIdx.x;
  const float4* p = (const float4*)(states + (long long)b * DIM);
  float s = 0.f;
  for (int k = threadIdx.x; k < DIM / 4; k += 256) {
    float4 v = p[k];
    s += v.x * v.x + v.y * v.y + v.z * v.z + v.w * v.w;
  }
  red[threadIdx.x] = s;
  __syncthreads();
  for (int off = 128; off; off >>= 1) {
    if (threadIdx.x < off) red[threadIdx.x] += red[threadIdx.x + off];
    __syncthreads();
  }
  if (threadIdx.x == 0) g_norminv[b] = rsqrtf(red[0]);
}

// P1 (tile A): pre-rotations, ascending 6-CNOT chain (b4..b10), post RX b4,b5
__global__ void __launch_bounds__(NT) kP1(const float* states) {
  extern __shared__ float2 t[];
  int b = blockIdx.x >> 2, o = blockIdx.x & 3;
  float ninv = g_norminv[b];
  const float4* gp = (const float4*)(states + (long long)b * DIM + o * TILE);
  for (int k = threadIdx.x; k < TILE / 4; k += NT) {
    float4 v = gp[k];
    int i = 4 * k;
    t[sw(i + 0)] = make_float2(v.x * ninv, 0.f);
    t[sw(i + 1)] = make_float2(v.y * ninv, 0.f);
    t[sw(i + 2)] = make_float2(v.z * ninv, 0.f);
    t[sw(i + 3)] = make_float2(v.w * ninv, 0.f);
  }
  usweep<4, 1, 2, 4, 8>(t, 0);
  usweep<4, 1024, 2048, 4096, 8192>(t, 4);
  permchain<true>(t);
  usweep<2, 16, 32, 64, 128>(t, 8);     // only first 2 wires used: NW=2
  __syncthreads();
  storeA(t, b, o);
}

// P2 (tile B): 14 per-wire composites, trailing 3-CNOT chain folded into store
__global__ void __launch_bounds__(NT) kP2() {
  extern __shared__ float2 t[];
  int b = blockIdx.x >> 2, o = blockIdx.x & 3;
  loadB(t, b, o, 0);
  usweep<4, 1, 2, 4, 8>(t, 10);
  usweep<4, 16, 32, 64, 128>(t, 14);
  usweep<4, 256, 512, 1024, 2048>(t, 18);
  usweep<2, 4096, 8192, 0x4000, 0x8000>(t, 22);
  __syncthreads();
  storeB(t, b, o, 0x1C00);
}

// P3 (tile A): RX b10,b11; 12-CNOT ladder; RY on b1..b13
__global__ void __launch_bounds__(NT) kP3() {
  extern __shared__ float2 t[];
  int b = blockIdx.x >> 2, o = blockIdx.x & 3;
  loadA(t, b, o);
  usweep<2, 1024, 2048, 0x4000, 0x8000>(t, 24);
  permchain<false>(t);
  usweep<4, 2, 4, 8, 16>(t, 26);
  usweep<4, 32, 64, 128, 256>(t, 30);
  usweep<4, 512, 1024, 2048, 4096>(t, 34);
  usweep<1, 8192, 0x4000, 0x8000, 0x10000>(t, 38);
  __syncthreads();
  storeA(t, b, o);
}

// P4 (tile B): lead CNOT folded into load; 14 composites; trailing chain in store
__global__ void __launch_bounds__(NT) kP4() {
  extern __shared__ float2 t[];
  int b = blockIdx.x >> 2, o = blockIdx.x & 3;
  loadB(t, b, o, 1);
  usweep<4, 2, 4, 8, 16>(t, 39);
  usweep<4, 32, 64, 128, 256>(t, 43);
  usweep<4, 512, 1024, 2048, 4096>(t, 47);
  usweep<2, 1, 8192, 0x4000, 0x8000>(t, 51);
  __syncthreads();
  storeB(t, b, o, 0x1C00);
}

// Measure: cross-tile X (pre-P5, commutes), P5 in smem, Z + in-tile X.
__global__ void __launch_bounds__(NT) kMeasure() {
  extern __shared__ float2 t[];
  int b = blockIdx.x >> 2, o = blockIdx.x & 3;
  loadA(t, b, o);
  __syncthreads();

  float zacc[16], xacc[16];
#pragma unroll
  for (int w = 0; w < 16; ++w) { zacc[w] = 0.f; xacc[w] = 0.f; }

  const float2* base = g_psi + (long long)b * DIM;
  if (o < 2) {      // bit15==0: Xop_0 = X_b15 ; Xop_15 = X_b15 X_b0
    float a0 = 0.f, a15 = 0.f;
    for (int l = threadIdx.x; l < TILE; l += NT) {
      int i = (o << 14) | l;
      float2 a = t[sw(l)];
      float2 p0 = base[i | 0x8000];
      float2 p1 = base[(i | 0x8000) ^ 1];
      a0 += a.x * p0.x + a.y * p0.y;
      a15 += a.x * p1.x + a.y * p1.y;
    }
    xacc[0] = 2.f * a0;
    xacc[15] = 2.f * a15;
  }
  if ((o & 1) == 0) {  // bit14==0: Xop_1 = X_b14
    float a1 = 0.f;
    for (int l = threadIdx.x; l < TILE; l += NT) {
      int i = (o << 14) | l;
      float2 a = t[sw(l)];
      float2 p = base[i | 0x4000];
      a1 += a.x * p.x + a.y * p.y;
    }
    xacc[1] = 2.f * a1;
  }

  // P5: RX b10,b11 + 12-CNOT ladder (usweep has leading sync)
  usweep<2, 1024, 2048, 0x4000, 0x8000>(t, 53);
  permchain<false>(t);
  __syncthreads();

  for (int l = threadIdx.x; l < TILE; l += NT) {
    float2 a = t[sw(l)];
    float p = a.x * a.x + a.y * a.y;
    int i = (o << 14) | l;
    zacc[0] += (((i >> 15) ^ i) & 1) ? -p : p;
#pragma unroll
    for (int w = 1; w < 16; ++w)
      zacc[w] += ((i >> (15 - w)) & 1) ? -p : p;
  }

#pragma unroll
  for (int w = 2; w <= 14; ++w) {
    const int m = 1 << (15 - w);
    float acc = 0.f;
    for (int q = threadIdx.x; q < TILE / 2; q += NT) {
      int i0 = ((q & ~(m - 1)) << 1) | (q & (m - 1));
      float2 a = t[sw(i0)], bb = t[sw(i0 | m)];
      acc += a.x * bb.x + a.y * bb.y;
    }
    xacc[w] = 2.f * acc;
  }

  __syncthreads();
  float* red = (float*)t;
  int lane = threadIdx.x & 31, wid = threadIdx.x >> 5;
#pragma unroll
  for (int v = 0; v < 32; ++v) {
    float val = (v < 16) ? zacc[v] : xacc[v - 16];
#pragma unroll
    for (int off = 16; off; off >>= 1) val += __shfl_down_sync(0xffffffffu, val, off);
    if (lane == 0) red[wid * 32 + v] = val;
  }
  __syncthreads();
  if (threadIdx.x < 32) {
    int v = threadIdx.x;
    float s = 0.f;
    for (int w = 0; w < NT / 32; ++w) s += red[w * 32 + v];
    g_part[blockIdx.x * 32 + v] = s;
  }
}

__global__ void __launch_bounds__(128) kHead(
    const float* theta_ry, const float* w1, const float* b1,
    const float* w2, const float* b2, const float* g1, const float* be1,
    const float* g2, const float* be2, const float* wh, const float* bh,
    float* out) {
  int b = blockIdx.x * blockDim.x + threadIdx.x;
  if (b >= BSZ) return;

  float attn[16], xs[16];
#pragma unroll
  for (int w = 0; w < 16; ++w) {
    float za = 0.f, xa = 0.f;
#pragma unroll
    for (int o = 0; o < 4; ++o) {
      za += g_part[(b * 4 + o) * 32 + w];
      xa += g_part[(b * 4 + o) * 32 + 16 + w];
    }
    attn[w] = za; xs[w] = xa;
  }
  float th = theta_ry[1];
  float cb = cosf(th), sb = sinf(th);
  float m[16];
#pragma unroll
  for (int w = 0; w < 16; ++w) m[w] = cb * attn[w] - sb * xs[w];

  float mu = 0.f;
#pragma unroll
  for (int w = 0; w < 16; ++w) mu += attn[w];
  mu *= (1.f / 16.f);
  float var = 0.f;
#pragma unroll
  for (int w = 0; w < 16; ++w) { float d = attn[w] - mu; var += d * d; }
  var *= (1.f / 16.f);
  float rs = rsqrtf(var + 1e-5f);
  float x[16];
#pragma unroll
  for (int w = 0; w < 16; ++w) x[w] = (attn[w] - mu) * rs * g1[16 + w] + be1[16 + w];

  float ffn[16];
#pragma unroll
  for (int w = 0; w < 16; ++w) ffn[w] = b2[16 + w];
  for (int j = 0; j < 64; ++j) {
    float h = b1[64 + j];
#pragma unroll
    for (int w = 0; w < 16; ++w) h += m[w] * w1[1024 + j * 16 + w];
    h = fmaxf(h, 0.f);
#pragma unroll
    for (int w = 0; w < 16; ++w) ffn[w] += h * w2[1024 + w * 64 + j];
  }

  float y[16];
#pragma unroll
  for (int w = 0; w < 16; ++w) y[w] = x[w] + ffn[w];
  float mu2 = 0.f;
#pragma unroll
  for (int w = 0; w < 16; ++w) mu2 += y[w];
  mu2 *= (1.f / 16.f);
  float var2 = 0.f;
#pragma unroll
  for (int w = 0; w < 16; ++w) { float d = y[w] - mu2; var2 += d * d; }
  var2 *= (1.f / 16.f);
  float rs2 = rsqrtf(var2 + 1e-5f);

  float ov = bh[0];
#pragma unroll
  for (int w = 0; w < 16; ++w)
    ov += ((y[w] - mu2) * rs2 * g2[16 + w] + be2[16 + w]) * wh[w];
  out[b] = ov;
}

extern "C" void kernel_launch(void* const* d_in, const int* in_sizes, int n_in,
                              void* d_out, int out_size) {
  const float* states = (const float*)d_in[0];
  const float* ra     = (const float*)d_in[1];
  const float* trx    = (const float*)d_in[2];
  const float* try_   = (const float*)d_in[3];
  const float* w1     = (const float*)d_in[4];
  const float* b1     = (const float*)d_in[5];
  const float* w2     = (const float*)d_in[6];
  const float* b2     = (const float*)d_in[7];
  const float* g1     = (const float*)d_in[8];
  const float* be1    = (const float*)d_in[9];
  const float* g2     = (const float*)d_in[10];
  const float* be2    = (const float*)d_in[11];
  const float* wh     = (const float*)d_in[12];
  const float* bh     = (const float*)d_in[13];
  float* out = (float*)d_out;

  cudaFuncSetAttribute(kP1, cudaFuncAttributeMaxDynamicSharedMemorySize, SMEM_BYTES);
  cudaFuncSetAttribute(kP2, cudaFuncAttributeMaxDynamicSharedMemorySize, SMEM_BYTES);
  cudaFuncSetAttribute(kP3, cudaFuncAttributeMaxDynamicSharedMemorySize, SMEM_BYTES);
  cudaFuncSetAttribute(kP4, cudaFuncAttributeMaxDynamicSharedMemorySize, SMEM_BYTES);
  cudaFuncSetAttribute(kMeasure, cudaFuncAttributeMaxDynamicSharedMemorySize, SMEM_BYTES);

  kSetup<<<1, 32>>>(ra, trx, try_);
  kNorm<<<BSZ, 256>>>(states);
  kP1<<<BSZ * 4, NT, SMEM_BYTES>>>(states);
  kP2<<<BSZ * 4, NT, SMEM_BYTES>>>();
  kP3<<<BSZ * 4, NT, SMEM_BYTES>>>();
  kP4<<<BSZ * 4, NT, SMEM_BYTES>>>();
  kMeasure<<<BSZ * 4, NT, SMEM_BYTES>>>();
  kHead<<<(BSZ + 127) / 128, 128>>>(try_, w1, b1, w2, b2, g1, be1, g2, be2, wh, bh, out);
}

// round 12
// speedup vs baseline: 1.8847x; 1.0648x over previous
#include <cuda_runtime.h>

#define BSZ 512
#define DIM 65536
#define NTP 1024
#define NTM 512
#define TILE 16384
#define SMEM_BYTES (TILE * 8)

__device__ float2 g_psi[(long long)BSZ * DIM];   // 256 MB scratch statevector
__device__ float  g_norminv[BSZ];
__device__ float2 g_Umat[56][4];                 // per-wire composite 2x2 unitaries
__device__ float  g_part[BSZ * 4 * 32];

__device__ __forceinline__ int sw(int l) { return l ^ ((l >> 4) & 15); }

// ---- 2x2 complex helpers (setup only) ----
struct C2 { float2 a, b, c, d; };
__device__ __forceinline__ float2 cmul(float2 x, float2 y) {
  return make_float2(x.x * y.x - x.y * y.y, x.x * y.y + x.y * y.x);
}
__device__ __forceinline__ float2 cad(float2 x, float2 y) { return make_float2(x.x + y.x, x.y + y.y); }
__device__ C2 mmul(C2 X, C2 Y) {   // X*Y (Y applied first)
  C2 r;
  r.a = cad(cmul(X.a, Y.a), cmul(X.b, Y.c));
  r.b = cad(cmul(X.a, Y.b), cmul(X.b, Y.d));
  r.c = cad(cmul(X.c, Y.a), cmul(X.d, Y.c));
  r.d = cad(cmul(X.c, Y.b), cmul(X.d, Y.d));
  return r;
}

// Setup: composite unitary table (same slot layout as R11).
__global__ void kSetup(const float* ra, const float* trx, const float* try_) {
  if (threadIdx.x) return;
  float2 tg[24];
  for (int i = 0; i < 24; i++) {
    float a = (i < 20) ? ra[i] : (i < 22 ? trx[i - 20] : try_[i - 22]);
    tg[i] = make_float2(cosf(a * 0.5f), sinf(a * 0.5f));
  }
#define MRX(i) C2{make_float2(tg[i].x,0.f), make_float2(0.f,-tg[i].y), make_float2(0.f,-tg[i].y), make_float2(tg[i].x,0.f)}
#define MRY(i) C2{make_float2(tg[i].x,0.f), make_float2(-tg[i].y,0.f), make_float2(tg[i].y,0.f), make_float2(tg[i].x,0.f)}
  C2 M[56];
  M[0] = mmul(MRY(19), MRX(3));
  M[1] = MRX(6);  M[2] = MRX(9);  M[3] = MRX(12);
  M[4] = MRY(1);  M[5] = MRY(4);  M[6] = MRY(7);  M[7] = MRY(10);
  M[8] = MRX(15); M[9] = MRX(18);
  for (int k = 10; k <= 21; k++) M[k] = MRX(20);
  M[22] = mmul(MRX(20), MRY(13));
  M[23] = mmul(MRX(20), mmul(MRY(16), MRX(0)));
  M[24] = MRX(20); M[25] = MRX(20);
  for (int k = 26; k <= 38; k++) M[k] = MRY(22);
  for (int k = 39; k <= 49; k++) M[k] = MRX(21);
  M[50] = mmul(MRX(21), MRY(22));
  M[51] = M[50]; M[52] = M[50];
  M[53] = MRX(21); M[54] = MRX(21);
  for (int k = 0; k < 55; k++) {
    g_Umat[k][0] = M[k].a; g_Umat[k][1] = M[k].b;
    g_Umat[k][2] = M[k].c; g_Umat[k][3] = M[k].d;
  }
}

// ---- static sweep: NW general unitaries on compile-time masks (ascending) ----
template<int NTT, int NW, int M0, int M1, int M2, int M3>
__device__ __forceinline__ void usweep(float2* t, int ubase) {
  constexpr int NA = 1 << NW;
  constexpr int ITERS = (TILE >> NW) / NTT;
  float2 U[NW][4];
#pragma unroll
  for (int k = 0; k < NW; k++)
#pragma unroll
    for (int e = 0; e < 4; e++) U[k][e] = g_Umat[ubase + k][e];
  __syncthreads();
#pragma unroll
  for (int it = 0; it < ITERS; it++) {
    int q = threadIdx.x + it * NTT;
    int idx = q;
    idx = ((idx & ~(M0 - 1)) << 1) | (idx & (M0 - 1));
    if (NW > 1) idx = ((idx & ~(M1 - 1)) << 1) | (idx & (M1 - 1));
    if (NW > 2) idx = ((idx & ~(M2 - 1)) << 1) | (idx & (M2 - 1));
    if (NW > 3) idx = ((idx & ~(M3 - 1)) << 1) | (idx & (M3 - 1));
    const int MS[4] = {M0, M1, M2, M3};
    float2 v[NA];
#pragma unroll
    for (int j = 0; j < NA; j++) {
      int off = 0;
#pragma unroll
      for (int k = 0; k < NW; k++) if ((j >> k) & 1) off |= MS[k];
      v[j] = t[sw(idx | off)];
    }
#pragma unroll
    for (int k = 0; k < NW; k++) {
      const float2 u00 = U[k][0], u01 = U[k][1], u10 = U[k][2], u11 = U[k][3];
#pragma unroll
      for (int j = 0; j < NA; j++) if (!((j >> k) & 1)) {
        float2 a = v[j], b = v[j | (1 << k)];
        v[j] = make_float2(
          u00.x * a.x - u00.y * a.y + u01.x * b.x - u01.y * b.y,
          u00.x * a.y + u00.y * a.x + u01.x * b.y + u01.y * b.x);
        v[j | (1 << k)] = make_float2(
          u10.x * a.x - u10.y * a.y + u11.x * b.x - u11.y * b.y,
          u10.x * a.y + u10.y * a.x + u11.x * b.y + u11.y * b.x);
      }
    }
#pragma unroll
    for (int j = 0; j < NA; j++) {
      int off = 0;
#pragma unroll
      for (int k = 0; k < NW; k++) if ((j >> k) & 1) off |= MS[k];
      t[sw(idx | off)] = v[j];
    }
  }
}

// CNOT-chain permutation sweep.
template<bool ASC, int NTT>
__device__ __forceinline__ void permchain(float2* t) {
  __syncthreads();
  constexpr int PER = TILE / NTT;
  float2 v[PER];
  int d0 = threadIdx.x * PER;
#pragma unroll
  for (int j = 0; j < PER; j++) {
    int d = d0 + j, src;
    if (ASC) {
      src = d;
#pragma unroll
      for (int k = 9; k >= 4; k--) src ^= (src >> 1) & (1 << k);
    } else {
      src = d ^ ((d >> 1) & 0x0FFF);
    }
    v[j] = t[sw(src)];
  }
  __syncthreads();
#pragma unroll
  for (int j = 0; j < PER; j++) t[sw(d0 + j)] = v[j];
}

// ---- global <-> smem tile movement (smem swizzled) ----
__device__ __forceinline__ void loadA(float2* t, int b, int o) {
  const float4* gp = (const float4*)(g_psi + (long long)b * DIM + o * TILE);
  for (int k = threadIdx.x; k < TILE / 2; k += blockDim.x) {
    float4 w4 = gp[k];
    t[sw(2 * k)]     = make_float2(w4.x, w4.y);
    t[sw(2 * k + 1)] = make_float2(w4.z, w4.w);
  }
}
__device__ __forceinline__ void storeA(const float2* t, int b, int o) {
  float4* gp = (float4*)(g_psi + (long long)b * DIM + o * TILE);
  for (int k = threadIdx.x; k < TILE / 2; k += blockDim.x) {
    float2 a = t[sw(2 * k)], c = t[sw(2 * k + 1)];
    gp[k] = make_float4(a.x, a.y, c.x, c.y);
  }
}
__device__ __forceinline__ void loadB(float2* t, int b, int o, int lead) {
  const float2* base = g_psi + (long long)b * DIM + (o << 10);
  for (int k = threadIdx.x; k < TILE / 2; k += blockDim.x) {
    int s = 2 * k;
    int r = s >> 10, lo = s & 1023;
    float4 w4 = *(const float4*)(base + (r << 12) + lo);
    t[sw(s)] = make_float2(w4.x, w4.y);
    int d1 = (s + 1) ^ (lead << 13);
    t[sw(d1)] = make_float2(w4.z, w4.w);
  }
}
__device__ __forceinline__ void storeB(const float2* t, int b, int o, int foldmask) {
  float2* base = g_psi + (long long)b * DIM + (o << 10);
  for (int k = threadIdx.x; k < TILE / 2; k += blockDim.x) {
    int d = 2 * k;
    int src = d ^ ((d >> 1) & foldmask);
    float2 a = t[sw(src)], c = t[sw(src + 1)];
    int r = d >> 10, lo = d & 1023;
    *(float4*)(base + (r << 12) + lo) = make_float4(a.x, a.y, c.x, c.y);
  }
}

// ---- kernels ----
__global__ void __launch_bounds__(256) kNorm(const float* states) {
  __shared__ float red[256];
  int b = blockIdx.x;
  const float4* p = (const float4*)(states + (long long)b * DIM);
  float s = 0.f;
  for (int k = threadIdx.x; k < DIM / 4; k += 256) {
    float4 v = p[k];
    s += v.x * v.x + v.y * v.y + v.z * v.z + v.w * v.w;
  }
  red[threadIdx.x] = s;
  __syncthreads();
  for (int off = 128; off; off >>= 1) {
    if (threadIdx.x < off) red[threadIdx.x] += red[threadIdx.x + off];
    __syncthreads();
  }
  if (threadIdx.x == 0) g_norminv[b] = rsqrtf(red[0]);
}

__global__ void __launch_bounds__(NTP) kP1(const float* states) {
  extern __shared__ float2 t[];
  int b = blockIdx.x >> 2, o = blockIdx.x & 3;
  float ninv = g_norminv[b];
  const float4* gp = (const float4*)(states + (long long)b * DIM + o * TILE);
  for (int k = threadIdx.x; k < TILE / 4; k += NTP) {
    float4 v = gp[k];
    int i = 4 * k;
    t[sw(i + 0)] = make_float2(v.x * ninv, 0.f);
    t[sw(i + 1)] = make_float2(v.y * ninv, 0.f);
    t[sw(i + 2)] = make_float2(v.z * ninv, 0.f);
    t[sw(i + 3)] = make_float2(v.w * ninv, 0.f);
  }
  usweep<NTP, 4, 1, 2, 4, 8>(t, 0);
  usweep<NTP, 4, 1024, 2048, 4096, 8192>(t, 4);
  permchain<true, NTP>(t);
  usweep<NTP, 2, 16, 32, 64, 128>(t, 8);
  __syncthreads();
  storeA(t, b, o);
}

__global__ void __launch_bounds__(NTP) kP2() {
  extern __shared__ float2 t[];
  int b = blockIdx.x >> 2, o = blockIdx.x & 3;
  loadB(t, b, o, 0);
  usweep<NTP, 4, 1, 2, 4, 8>(t, 10);
  usweep<NTP, 4, 16, 32, 64, 128>(t, 14);
  usweep<NTP, 4, 256, 512, 1024, 2048>(t, 18);
  usweep<NTP, 2, 4096, 8192, 0x4000, 0x8000>(t, 22);
  __syncthreads();
  storeB(t, b, o, 0x1C00);
}

__global__ void __launch_bounds__(NTP) kP3() {
  extern __shared__ float2 t[];
  int b = blockIdx.x >> 2, o = blockIdx.x & 3;
  loadA(t, b, o);
  usweep<NTP, 2, 1024, 2048, 0x4000, 0x8000>(t, 24);
  permchain<false, NTP>(t);
  usweep<NTP, 4, 2, 4, 8, 16>(t, 26);
  usweep<NTP, 4, 32, 64, 128, 256>(t, 30);
  usweep<NTP, 4, 512, 1024, 2048, 4096>(t, 34);
  usweep<NTP, 1, 8192, 0x4000, 0x8000, 0x10000>(t, 38);
  __syncthreads();
  storeA(t, b, o);
}

__global__ void __launch_bounds__(NTP) kP4() {
  extern __shared__ float2 t[];
  int b = blockIdx.x >> 2, o = blockIdx.x & 3;
  loadB(t, b, o, 1);
  usweep<NTP, 4, 2, 4, 8, 16>(t, 39);
  usweep<NTP, 4, 32, 64, 128, 256>(t, 43);
  usweep<NTP, 4, 512, 1024, 2048, 4096>(t, 47);
  usweep<NTP, 2, 1, 8192, 0x4000, 0x8000>(t, 51);
  __syncthreads();
  storeB(t, b, o, 0x1C00);
}

// Measure: cross-tile X (pre-P5, commutes), P5 in smem, Z + grouped in-tile X.
__global__ void __launch_bounds__(NTM) kMeasure() {
  extern __shared__ float2 t[];
  int b = blockIdx.x >> 2, o = blockIdx.x & 3;
  loadA(t, b, o);
  __syncthreads();

  float zacc[16], xacc[16];
#pragma unroll
  for (int w = 0; w < 16; ++w) { zacc[w] = 0.f; xacc[w] = 0.f; }

  const float2* base = g_psi + (long long)b * DIM;
  if (o < 2) {      // bit15==0: Xop_0 = X_b15 ; Xop_15 = X_b15 X_b0
    float a0 = 0.f, a15 = 0.f;
    for (int l = threadIdx.x; l < TILE; l += NTM) {
      int i = (o << 14) | l;
      float2 a = t[sw(l)];
      float2 p0 = base[i | 0x8000];
      float2 p1 = base[(i | 0x8000) ^ 1];
      a0 += a.x * p0.x + a.y * p0.y;
      a15 += a.x * p1.x + a.y * p1.y;
    }
    xacc[0] = 2.f * a0;
    xacc[15] = 2.f * a15;
  }
  if ((o & 1) == 0) {  // bit14==0: Xop_1 = X_b14
    float a1 = 0.f;
    for (int l = threadIdx.x; l < TILE; l += NTM) {
      int i = (o << 14) | l;
      float2 a = t[sw(l)];
      float2 p = base[i | 0x4000];
      a1 += a.x * p.x + a.y * p.y;
    }
    xacc[1] = 2.f * a1;
  }

  // P5: RX b10,b11 + 12-CNOT ladder (usweep has leading sync)
  usweep<NTM, 2, 1024, 2048, 0x4000, 0x8000>(t, 53);
  permchain<false, NTM>(t);
  __syncthreads();

  // Pass A: bits {1..4} -> X for w=14..11, Z fused (full-tile read)
  for (int q = threadIdx.x; q < TILE / 16; q += NTM) {
    int idx = (q & 1) | ((q & ~1) << 4);
    float2 v[16];
#pragma unroll
    for (int j = 0; j < 16; j++) v[j] = t[sw(idx | (j << 1))];
#pragma unroll
    for (int j = 0; j < 16; j++) {
      float2 a = v[j];
      float p = a.x * a.x + a.y * a.y;
      int i = (o << 14) | idx | (j << 1);
      zacc[0] += (((i >> 15) ^ i) & 1) ? -p : p;
#pragma unroll
      for (int w = 1; w < 16; ++w)
        zacc[w] += ((i >> (15 - w)) & 1) ? -p : p;
    }
#pragma unroll
    for (int k = 0; k < 4; k++) {
      float acc = 0.f;
#pragma unroll
      for (int j = 0; j < 16; j++) if (!((j >> k) & 1)) {
        float2 a = v[j], c = v[j | (1 << k)];
        acc += a.x * c.x + a.y * c.y;
      }
      xacc[14 - k] += 2.f * acc;
    }
  }
  // Pass B: bits {5..8} -> X for w=10..7
  for (int q = threadIdx.x; q < TILE / 16; q += NTM) {
    int idx = (q & 31) | ((q & ~31) << 4);
    float2 v[16];
#pragma unroll
    for (int j = 0; j < 16; j++) v[j] = t[sw(idx | (j << 5))];
#pragma unroll
    for (int k = 0; k < 4; k++) {
      float acc = 0.f;
#pragma unroll
      for (int j = 0; j < 16; j++) if (!((j >> k) & 1)) {
        float2 a = v[j], c = v[j | (1 << k)];
        acc += a.x * c.x + a.y * c.y;
      }
      xacc[10 - k] += 2.f * acc;
    }
  }
  // Pass C: bits {9..12} -> X for w=6..3
  for (int q = threadIdx.x; q < TILE / 16; q += NTM) {
    int idx = (q & 511) | ((q & ~511) << 4);
    float2 v[16];
#pragma unroll
    for (int j = 0; j < 16; j++) v[j] = t[sw(idx | (j << 9))];
#pragma unroll
    for (int k = 0; k < 4; k++) {
      float acc = 0.f;
#pragma unroll
      for (int j = 0; j < 16; j++) if (!((j >> k) & 1)) {
        float2 a = v[j], c = v[j | (1 << k)];
        acc += a.x * c.x + a.y * c.y;
      }
      xacc[6 - k] += 2.f * acc;
    }
  }
  // Pass D: mask 8192 -> w=2
  {
    float acc = 0.f;
    for (int q = threadIdx.x; q < TILE / 2; q += NTM) {
      float2 a = t[sw(q)], c = t[sw(q | 8192)];
      acc += a.x * c.x + a.y * c.y;
    }
    xacc[2] = 2.f * acc;
  }

  __syncthreads();
  float* red = (float*)t;
  int lane = threadIdx.x & 31, wid = threadIdx.x >> 5;
#pragma unroll
  for (int v = 0; v < 32; ++v) {
    float val = (v < 16) ? zacc[v] : xacc[v - 16];
#pragma unroll
    for (int off = 16; off; off >>= 1) val += __shfl_down_sync(0xffffffffu, val, off);
    if (lane == 0) red[wid * 32 + v] = val;
  }
  __syncthreads();
  if (threadIdx.x < 32) {
    int v = threadIdx.x;
    float s = 0.f;
    for (int w = 0; w < NTM / 32; ++w) s += red[w * 32 + v];
    g_part[blockIdx.x * 32 + v] = s;
  }
}

__global__ void __launch_bounds__(128) kHead(
    const float* theta_ry, const float* w1, const float* b1,
    const float* w2, const float* b2, const float* g1, const float* be1,
    const float* g2, const float* be2, const float* wh, const float* bh,
    float* out) {
  int b = blockIdx.x * blockDim.x + threadIdx.x;
  if (b >= BSZ) return;

  float attn[16], xs[16];
#pragma unroll
  for (int w = 0; w < 16; ++w) {
    float za = 0.f, xa = 0.f;
#pragma unroll
    for (int o = 0; o < 4; ++o) {
      za += g_part[(b * 4 + o) * 32 + w];
      xa += g_part[(b * 4 + o) * 32 + 16 + w];
    }
    attn[w] = za; xs[w] = xa;
  }
  float th = theta_ry[1];
  float cb = cosf(th), sb = sinf(th);
  float m[16];
#pragma unroll
  for (int w = 0; w < 16; ++w) m[w] = cb * attn[w] - sb * xs[w];

  float mu = 0.f;
#pragma unroll
  for (int w = 0; w < 16; ++w) mu += attn[w];
  mu *= (1.f / 16.f);
  float var = 0.f;
#pragma unroll
  for (int w = 0; w < 16; ++w) { float d = attn[w] - mu; var += d * d; }
  var *= (1.f / 16.f);
  float rs = rsqrtf(var + 1e-5f);
  float x[16];
#pragma unroll
  for (int w = 0; w < 16; ++w) x[w] = (attn[w] - mu) * rs * g1[16 + w] + be1[16 + w];

  float ffn[16];
#pragma unroll
  for (int w = 0; w < 16; ++w) ffn[w] = b2[16 + w];
  for (int j = 0; j < 64; ++j) {
    float h = b1[64 + j];
#pragma unroll
    for (int w = 0; w < 16; ++w) h += m[w] * w1[1024 + j * 16 + w];
    h = fmaxf(h, 0.f);
#pragma unroll
    for (int w = 0; w < 16; ++w) ffn[w] += h * w2[1024 + w * 64 + j];
  }

  float y[16];
#pragma unroll
  for (int w = 0; w < 16; ++w) y[w] = x[w] + ffn[w];
  float mu2 = 0.f;
#pragma unroll
  for (int w = 0; w < 16; ++w) mu2 += y[w];
  mu2 *= (1.f / 16.f);
  float var2 = 0.f;
#pragma unroll
  for (int w = 0; w < 16; ++w) { float d = y[w] - mu2; var2 += d * d; }
  var2 *= (1.f / 16.f);
  float rs2 = rsqrtf(var2 + 1e-5f);

  float ov = bh[0];
#pragma unroll
  for (int w = 0; w < 16; ++w)
    ov += ((y[w] - mu2) * rs2 * g2[16 + w] + be2[16 + w]) * wh[w];
  out[b] = ov;
}

extern "C" void kernel_launch(void* const* d_in, const int* in_sizes, int n_in,
                              void* d_out, int out_size) {
  const float* states = (const float*)d_in[0];
  const float* ra     = (const float*)d_in[1];
  const float* trx    = (const float*)d_in[2];
  const float* try_   = (const float*)d_in[3];
  const float* w1     = (const float*)d_in[4];
  const float* b1     = (const float*)d_in[5];
  const float* w2     = (const float*)d_in[6];
  const float* b2     = (const float*)d_in[7];
  const float* g1     = (const float*)d_in[8];
  const float* be1    = (const float*)d_in[9];
  const float* g2     = (const float*)d_in[10];
  const float* be2    = (const float*)d_in[11];
  const float* wh     = (const float*)d_in[12];
  const float* bh     = (const float*)d_in[13];
  float* out = (float*)d_out;

  cudaFuncSetAttribute(kP1, cudaFuncAttributeMaxDynamicSharedMemorySize, SMEM_BYTES);
  cudaFuncSetAttribute(kP2, cudaFuncAttributeMaxDynamicSharedMemorySize, SMEM_BYTES);
  cudaFuncSetAttribute(kP3, cudaFuncAttributeMaxDynamicSharedMemorySize, SMEM_BYTES);
  cudaFuncSetAttribute(kP4, cudaFuncAttributeMaxDynamicSharedMemorySize, SMEM_BYTES);
  cudaFuncSetAttribute(kMeasure, cudaFuncAttributeMaxDynamicSharedMemorySize, SMEM_BYTES);

  kSetup<<<1, 32>>>(ra, trx, try_);
  kNorm<<<BSZ, 256>>>(states);
  kP1<<<BSZ * 4, NTP, SMEM_BYTES>>>(states);
  kP2<<<BSZ * 4, NTP, SMEM_BYTES>>>();
  kP3<<<BSZ * 4, NTP, SMEM_BYTES>>>();
  kP4<<<BSZ * 4, NTP, SMEM_BYTES>>>();
  kMeasure<<<BSZ * 4, NTM, SMEM_BYTES>>>();
  kHead<<<(BSZ + 127) / 128, 128>>>(try_, w1, b1, w2, b2, g1, be1, g2, be2, wh, bh, out);
}

// round 13
// speedup vs baseline: 2.1791x; 1.1562x over previous
#include <cuda_runtime.h>

#define BSZ 512
#define DIM 65536
#define NTP 512
#define NTM 512
#define TILE 16384
#define SMEM_BYTES (TILE * 8)

__device__ float2 g_psi[(long long)BSZ * DIM];   // 256 MB scratch statevector
__device__ float  g_norminv[BSZ];
__device__ float2 g_Upk[56][8];                  // packed f32x2 unitary constants
__device__ float  g_part[BSZ * 4 * 32];

__device__ __forceinline__ int sw(int l) { return l ^ ((l >> 4) & 15); }

typedef unsigned long long u64;
__device__ __forceinline__ u64 f2mul(u64 a, u64 b) {
  u64 d; asm("mul.rn.f32x2 %0,%1,%2;" : "=l"(d) : "l"(a), "l"(b)); return d;
}
__device__ __forceinline__ u64 f2fma(u64 a, u64 b, u64 c) {
  u64 d; asm("fma.rn.f32x2 %0,%1,%2,%3;" : "=l"(d) : "l"(a), "l"(b), "l"(c)); return d;
}
__device__ __forceinline__ u64 swp(u64 a) { return (a >> 32) | (a << 32); }

// ---- 2x2 complex helpers (setup only) ----
struct C2 { float2 a, b, c, d; };
__device__ __forceinline__ float2 cmul(float2 x, float2 y) {
  return make_float2(x.x * y.x - x.y * y.y, x.x * y.y + x.y * y.x);
}
__device__ __forceinline__ float2 cad(float2 x, float2 y) { return make_float2(x.x + y.x, x.y + y.y); }
__device__ C2 mmul(C2 X, C2 Y) {   // X*Y (Y applied first)
  C2 r;
  r.a = cad(cmul(X.a, Y.a), cmul(X.b, Y.c));
  r.b = cad(cmul(X.a, Y.b), cmul(X.b, Y.d));
  r.c = cad(cmul(X.c, Y.a), cmul(X.d, Y.c));
  r.d = cad(cmul(X.c, Y.b), cmul(X.d, Y.d));
  return r;
}

// Setup: composite unitary table, stored pre-broadcast/pre-negated for f32x2.
// Slot layout identical to R11/R12.
__global__ void kSetup(const float* ra, const float* trx, const float* try_) {
  if (threadIdx.x) return;
  float2 tg[24];
  for (int i = 0; i < 24; i++) {
    float a = (i < 20) ? ra[i] : (i < 22 ? trx[i - 20] : try_[i - 22]);
    tg[i] = make_float2(cosf(a * 0.5f), sinf(a * 0.5f));
  }
#define MRX(i) C2{make_float2(tg[i].x,0.f), make_float2(0.f,-tg[i].y), make_float2(0.f,-tg[i].y), make_float2(tg[i].x,0.f)}
#define MRY(i) C2{make_float2(tg[i].x,0.f), make_float2(-tg[i].y,0.f), make_float2(tg[i].y,0.f), make_float2(tg[i].x,0.f)}
  C2 M[56];
  M[0] = mmul(MRY(19), MRX(3));
  M[1] = MRX(6);  M[2] = MRX(9);  M[3] = MRX(12);
  M[4] = MRY(1);  M[5] = MRY(4);  M[6] = MRY(7);  M[7] = MRY(10);
  M[8] = MRX(15); M[9] = MRX(18);
  for (int k = 10; k <= 21; k++) M[k] = MRX(20);
  M[22] = mmul(MRX(20), MRY(13));
  M[23] = mmul(MRX(20), mmul(MRY(16), MRX(0)));
  M[24] = MRX(20); M[25] = MRX(20);
  for (int k = 26; k <= 38; k++) M[k] = MRY(22);
  for (int k = 39; k <= 49; k++) M[k] = MRX(21);
  M[50] = mmul(MRX(21), MRY(22));
  M[51] = M[50]; M[52] = M[50];
  M[53] = MRX(21); M[54] = MRX(21);
  for (int k = 0; k < 55; k++) {
    float2 e[4] = {M[k].a, M[k].b, M[k].c, M[k].d};
    for (int i = 0; i < 4; i++) {
      g_Upk[k][2 * i]     = make_float2(e[i].x, e[i].x);    // broadcast real
      g_Upk[k][2 * i + 1] = make_float2(-e[i].y, e[i].y);   // (-imag, +imag)
    }
  }
}

// ---- f32x2 static sweep: NW general unitaries on compile-time masks (ascending) ----
template<int NTT, int NW, int M0, int M1, int M2, int M3>
__device__ __forceinline__ void usweepF(float2* t, int ubase) {
  constexpr int NA = 1 << NW;
  constexpr int ITERS = (TILE >> NW) / NTT;
  u64 U[NW][8];
#pragma unroll
  for (int k = 0; k < NW; k++)
#pragma unroll
    for (int e = 0; e < 8; e++) U[k][e] = *(const u64*)&g_Upk[ubase + k][e];
  __syncthreads();
#pragma unroll
  for (int it = 0; it < ITERS; it++) {
    int q = threadIdx.x + it * NTT;
    int idx = q;
    idx = ((idx & ~(M0 - 1)) << 1) | (idx & (M0 - 1));
    if (NW > 1) idx = ((idx & ~(M1 - 1)) << 1) | (idx & (M1 - 1));
    if (NW > 2) idx = ((idx & ~(M2 - 1)) << 1) | (idx & (M2 - 1));
    if (NW > 3) idx = ((idx & ~(M3 - 1)) << 1) | (idx & (M3 - 1));
    const int MS[4] = {M0, M1, M2, M3};
    u64 v[NA];
#pragma unroll
    for (int j = 0; j < NA; j++) {
      int off = 0;
#pragma unroll
      for (int k = 0; k < NW; k++) if ((j >> k) & 1) off |= MS[k];
      v[j] = *(const u64*)&t[sw(idx | off)];
    }
#pragma unroll
    for (int k = 0; k < NW; k++) {
#pragma unroll
      for (int j = 0; j < NA; j++) if (!((j >> k) & 1)) {
        u64 A = v[j], B = v[j | (1 << k)];
        u64 As = swp(A), Bs = swp(B);
        u64 nA = f2mul(U[k][0], A);
        nA = f2fma(U[k][1], As, nA);
        nA = f2fma(U[k][2], B, nA);
        nA = f2fma(U[k][3], Bs, nA);
        u64 nB = f2mul(U[k][4], A);
        nB = f2fma(U[k][5], As, nB);
        nB = f2fma(U[k][6], B, nB);
        nB = f2fma(U[k][7], Bs, nB);
        v[j] = nA; v[j | (1 << k)] = nB;
      }
    }
#pragma unroll
    for (int j = 0; j < NA; j++) {
      int off = 0;
#pragma unroll
      for (int k = 0; k < NW; k++) if ((j >> k) & 1) off |= MS[k];
      *(u64*)&t[sw(idx | off)] = v[j];
    }
  }
}

// CNOT-chain permutation sweep.
template<bool ASC, int NTT>
__device__ __forceinline__ void permchain(float2* t) {
  __syncthreads();
  constexpr int PER = TILE / NTT;
  float2 v[PER];
  int d0 = threadIdx.x * PER;
#pragma unroll
  for (int j = 0; j < PER; j++) {
    int d = d0 + j, src;
    if (ASC) {
      src = d;
#pragma unroll
      for (int k = 9; k >= 4; k--) src ^= (src >> 1) & (1 << k);
    } else {
      src = d ^ ((d >> 1) & 0x0FFF);
    }
    v[j] = t[sw(src)];
  }
  __syncthreads();
#pragma unroll
  for (int j = 0; j < PER; j++) t[sw(d0 + j)] = v[j];
}

// ---- global <-> smem tile movement (smem swizzled) ----
__device__ __forceinline__ void loadA(float2* t, int b, int o) {
  const float4* gp = (const float4*)(g_psi + (long long)b * DIM + o * TILE);
  for (int k = threadIdx.x; k < TILE / 2; k += blockDim.x) {
    float4 w4 = gp[k];
    t[sw(2 * k)]     = make_float2(w4.x, w4.y);
    t[sw(2 * k + 1)] = make_float2(w4.z, w4.w);
  }
}
__device__ __forceinline__ void storeA(const float2* t, int b, int o) {
  float4* gp = (float4*)(g_psi + (long long)b * DIM + o * TILE);
  for (int k = threadIdx.x; k < TILE / 2; k += blockDim.x) {
    float2 a = t[sw(2 * k)], c = t[sw(2 * k + 1)];
    gp[k] = make_float4(a.x, a.y, c.x, c.y);
  }
}
__device__ __forceinline__ void loadB(float2* t, int b, int o, int lead) {
  const float2* base = g_psi + (long long)b * DIM + (o << 10);
  for (int k = threadIdx.x; k < TILE / 2; k += blockDim.x) {
    int s = 2 * k;
    int r = s >> 10, lo = s & 1023;
    float4 w4 = *(const float4*)(base + (r << 12) + lo);
    t[sw(s)] = make_float2(w4.x, w4.y);
    int d1 = (s + 1) ^ (lead << 13);
    t[sw(d1)] = make_float2(w4.z, w4.w);
  }
}
__device__ __forceinline__ void storeB(const float2* t, int b, int o, int foldmask) {
  float2* base = g_psi + (long long)b * DIM + (o << 10);
  for (int k = threadIdx.x; k < TILE / 2; k += blockDim.x) {
    int d = 2 * k;
    int src = d ^ ((d >> 1) & foldmask);
    float2 a = t[sw(src)], c = t[sw(src + 1)];
    int r = d >> 10, lo = d & 1023;
    *(float4*)(base + (r << 12) + lo) = make_float4(a.x, a.y, c.x, c.y);
  }
}

// ---- kernels ----
__global__ void __launch_bounds__(256) kNorm(const float* states) {
  __shared__ float red[256];
  int b = blockIdx.x;
  const float4* p = (const float4*)(states + (long long)b * DIM);
  float s = 0.f;
  for (int k = threadIdx.x; k < DIM / 4; k += 256) {
    float4 v = p[k];
    s += v.x * v.x + v.y * v.y + v.z * v.z + v.w * v.w;
  }
  red[threadIdx.x] = s;
  __syncthreads();
  for (int off = 128; off; off >>= 1) {
    if (threadIdx.x < off) red[threadIdx.x] += red[threadIdx.x + off];
    __syncthreads();
  }
  if (threadIdx.x == 0) g_norminv[b] = rsqrtf(red[0]);
}

__global__ void __launch_bounds__(NTP) kP1(const float* states) {
  extern __shared__ float2 t[];
  int b = blockIdx.x >> 2, o = blockIdx.x & 3;
  float ninv = g_norminv[b];
  const float4* gp = (const float4*)(states + (long long)b * DIM + o * TILE);
  for (int k = threadIdx.x; k < TILE / 4; k += NTP) {
    float4 v = gp[k];
    int i = 4 * k;
    t[sw(i + 0)] = make_float2(v.x * ninv, 0.f);
    t[sw(i + 1)] = make_float2(v.y * ninv, 0.f);
    t[sw(i + 2)] = make_float2(v.z * ninv, 0.f);
    t[sw(i + 3)] = make_float2(v.w * ninv, 0.f);
  }
  usweepF<NTP, 4, 1, 2, 4, 8>(t, 0);
  usweepF<NTP, 4, 1024, 2048, 4096, 8192>(t, 4);
  permchain<true, NTP>(t);
  usweepF<NTP, 2, 16, 32, 64, 128>(t, 8);
  __syncthreads();
  storeA(t, b, o);
}

__global__ void __launch_bounds__(NTP) kP2() {
  extern __shared__ float2 t[];
  int b = blockIdx.x >> 2, o = blockIdx.x & 3;
  loadB(t, b, o, 0);
  usweepF<NTP, 4, 1, 2, 4, 8>(t, 10);
  usweepF<NTP, 4, 16, 32, 64, 128>(t, 14);
  usweepF<NTP, 4, 256, 512, 1024, 2048>(t, 18);
  usweepF<NTP, 2, 4096, 8192, 0x4000, 0x8000>(t, 22);
  __syncthreads();
  storeB(t, b, o, 0x1C00);
}

__global__ void __launch_bounds__(NTP) kP3() {
  extern __shared__ float2 t[];
  int b = blockIdx.x >> 2, o = blockIdx.x & 3;
  loadA(t, b, o);
  usweepF<NTP, 2, 1024, 2048, 0x4000, 0x8000>(t, 24);
  permchain<false, NTP>(t);
  usweepF<NTP, 4, 2, 4, 8, 16>(t, 26);
  usweepF<NTP, 4, 32, 64, 128, 256>(t, 30);
  usweepF<NTP, 4, 512, 1024, 2048, 4096>(t, 34);
  usweepF<NTP, 1, 8192, 0x4000, 0x8000, 0x10000>(t, 38);
  __syncthreads();
  storeA(t, b, o);
}

__global__ void __launch_bounds__(NTP) kP4() {
  extern __shared__ float2 t[];
  int b = blockIdx.x >> 2, o = blockIdx.x & 3;
  loadB(t, b, o, 1);
  usweepF<NTP, 4, 2, 4, 8, 16>(t, 39);
  usweepF<NTP, 4, 32, 64, 128, 256>(t, 43);
  usweepF<NTP, 4, 512, 1024, 2048, 4096>(t, 47);
  usweepF<NTP, 2, 1, 8192, 0x4000, 0x8000>(t, 51);
  __syncthreads();
  storeB(t, b, o, 0x1C00);
}

// Measure: cross-tile X (pre-P5, commutes), P5 in smem, Z + grouped in-tile X.
__global__ void __launch_bounds__(NTM) kMeasure() {
  extern __shared__ float2 t[];
  int b = blockIdx.x >> 2, o = blockIdx.x & 3;
  loadA(t, b, o);
  __syncthreads();

  float zacc[16], xacc[16];
#pragma unroll
  for (int w = 0; w < 16; ++w) { zacc[w] = 0.f; xacc[w] = 0.f; }

  const float2* base = g_psi + (long long)b * DIM;
  if (o < 2) {      // bit15==0: Xop_0 = X_b15 ; Xop_15 = X_b15 X_b0
    float a0 = 0.f, a15 = 0.f;
    for (int l = threadIdx.x; l < TILE; l += NTM) {
      int i = (o << 14) | l;
      float2 a = t[sw(l)];
      float2 p0 = base[i | 0x8000];
      float2 p1 = base[(i | 0x8000) ^ 1];
      a0 += a.x * p0.x + a.y * p0.y;
      a15 += a.x * p1.x + a.y * p1.y;
    }
    xacc[0] = 2.f * a0;
    xacc[15] = 2.f * a15;
  }
  if ((o & 1) == 0) {  // bit14==0: Xop_1 = X_b14
    float a1 = 0.f;
    for (int l = threadIdx.x; l < TILE; l += NTM) {
      int i = (o << 14) | l;
      float2 a = t[sw(l)];
      float2 p = base[i | 0x4000];
      a1 += a.x * p.x + a.y * p.y;
    }
    xacc[1] = 2.f * a1;
  }

  // P5: RX b10,b11 + 12-CNOT ladder (usweepF has leading sync)
  usweepF<NTM, 2, 1024, 2048, 0x4000, 0x8000>(t, 53);
  permchain<false, NTM>(t);
  __syncthreads();

  // Pass A: bits {1..4} -> X for w=14..11, Z fused (full-tile read)
  for (int q = threadIdx.x; q < TILE / 16; q += NTM) {
    int idx = (q & 1) | ((q & ~1) << 4);
    float2 v[16];
#pragma unroll
    for (int j = 0; j < 16; j++) v[j] = t[sw(idx | (j << 1))];
#pragma unroll
    for (int j = 0; j < 16; j++) {
      float2 a = v[j];
      float p = a.x * a.x + a.y * a.y;
      int i = (o << 14) | idx | (j << 1);
      zacc[0] += (((i >> 15) ^ i) & 1) ? -p : p;
#pragma unroll
      for (int w = 1; w < 16; ++w)
        zacc[w] += ((i >> (15 - w)) & 1) ? -p : p;
    }
#pragma unroll
    for (int k = 0; k < 4; k++) {
      float acc = 0.f;
#pragma unroll
      for (int j = 0; j < 16; j++) if (!((j >> k) & 1)) {
        float2 a = v[j], c = v[j | (1 << k)];
        acc += a.x * c.x + a.y * c.y;
      }
      xacc[14 - k] += 2.f * acc;
    }
  }
  // Pass B: bits {5..8} -> X for w=10..7
  for (int q = threadIdx.x; q < TILE / 16; q += NTM) {
    int idx = (q & 31) | ((q & ~31) << 4);
    float2 v[16];
#pragma unroll
    for (int j = 0; j < 16; j++) v[j] = t[sw(idx | (j << 5))];
#pragma unroll
    for (int k = 0; k < 4; k++) {
      float acc = 0.f;
#pragma unroll
      for (int j = 0; j < 16; j++) if (!((j >> k) & 1)) {
        float2 a = v[j], c = v[j | (1 << k)];
        acc += a.x * c.x + a.y * c.y;
      }
      xacc[10 - k] += 2.f * acc;
    }
  }
  // Pass C: bits {9..12} -> X for w=6..3
  for (int q = threadIdx.x; q < TILE / 16; q += NTM) {
    int idx = (q & 511) | ((q & ~511) << 4);
    float2 v[16];
#pragma unroll
    for (int j = 0; j < 16; j++) v[j] = t[sw(idx | (j << 9))];
#pragma unroll
    for (int k = 0; k < 4; k++) {
      float acc = 0.f;
#pragma unroll
      for (int j = 0; j < 16; j++) if (!((j >> k) & 1)) {
        float2 a = v[j], c = v[j | (1 << k)];
        acc += a.x * c.x + a.y * c.y;
      }
      xacc[6 - k] += 2.f * acc;
    }
  }
  // Pass D: mask 8192 -> w=2
  {
    float acc = 0.f;
    for (int q = threadIdx.x; q < TILE / 2; q += NTM) {
      float2 a = t[sw(q)], c = t[sw(q | 8192)];
      acc += a.x * c.x + a.y * c.y;
    }
    xacc[2] = 2.f * acc;
  }

  __syncthreads();
  float* red = (float*)t;
  int lane = threadIdx.x & 31, wid = threadIdx.x >> 5;
#pragma unroll
  for (int v = 0; v < 32; ++v) {
    float val = (v < 16) ? zacc[v] : xacc[v - 16];
#pragma unroll
    for (int off = 16; off; off >>= 1) val += __shfl_down_sync(0xffffffffu, val, off);
    if (lane == 0) red[wid * 32 + v] = val;
  }
  __syncthreads();
  if (threadIdx.x < 32) {
    int v = threadIdx.x;
    float s = 0.f;
    for (int w = 0; w < NTM / 32; ++w) s += red[w * 32 + v];
    g_part[blockIdx.x * 32 + v] = s;
  }
}

__global__ void __launch_bounds__(128) kHead(
    const float* theta_ry, const float* w1, const float* b1,
    const float* w2, const float* b2, const float* g1, const float* be1,
    const float* g2, const float* be2, const float* wh, const float* bh,
    float* out) {
  int b = blockIdx.x * blockDim.x + threadIdx.x;
  if (b >= BSZ) return;

  float attn[16], xs[16];
#pragma unroll
  for (int w = 0; w < 16; ++w) {
    float za = 0.f, xa = 0.f;
#pragma unroll
    for (int o = 0; o < 4; ++o) {
      za += g_part[(b * 4 + o) * 32 + w];
      xa += g_part[(b * 4 + o) * 32 + 16 + w];
    }
    attn[w] = za; xs[w] = xa;
  }
  float th = theta_ry[1];
  float cb = cosf(th), sb = sinf(th);
  float m[16];
#pragma unroll
  for (int w = 0; w < 16; ++w) m[w] = cb * attn[w] - sb * xs[w];

  float mu = 0.f;
#pragma unroll
  for (int w = 0; w < 16; ++w) mu += attn[w];
  mu *= (1.f / 16.f);
  float var = 0.f;
#pragma unroll
  for (int w = 0; w < 16; ++w) { float d = attn[w] - mu; var += d * d; }
  var *= (1.f / 16.f);
  float rs = rsqrtf(var + 1e-5f);
  float x[16];
#pragma unroll
  for (int w = 0; w < 16; ++w) x[w] = (attn[w] - mu) * rs * g1[16 + w] + be1[16 + w];

  float ffn[16];
#pragma unroll
  for (int w = 0; w < 16; ++w) ffn[w] = b2[16 + w];
  for (int j = 0; j < 64; ++j) {
    float h = b1[64 + j];
#pragma unroll
    for (int w = 0; w < 16; ++w) h += m[w] * w1[1024 + j * 16 + w];
    h = fmaxf(h, 0.f);
#pragma unroll
    for (int w = 0; w < 16; ++w) ffn[w] += h * w2[1024 + w * 64 + j];
  }

  float y[16];
#pragma unroll
  for (int w = 0; w < 16; ++w) y[w] = x[w] + ffn[w];
  float mu2 = 0.f;
#pragma unroll
  for (int w = 0; w < 16; ++w) mu2 += y[w];
  mu2 *= (1.f / 16.f);
  float var2 = 0.f;
#pragma unroll
  for (int w = 0; w < 16; ++w) { float d = y[w] - mu2; var2 += d * d; }
  var2 *= (1.f / 16.f);
  float rs2 = rsqrtf(var2 + 1e-5f);

  float ov = bh[0];
#pragma unroll
  for (int w = 0; w < 16; ++w)
    ov += ((y[w] - mu2) * rs2 * g2[16 + w] + be2[16 + w]) * wh[w];
  out[b] = ov;
}

extern "C" void kernel_launch(void* const* d_in, const int* in_sizes, int n_in,
                              void* d_out, int out_size) {
  const float* states = (const float*)d_in[0];
  const float* ra     = (const float*)d_in[1];
  const float* trx    = (const float*)d_in[2];
  const float* try_   = (const float*)d_in[3];
  const float* w1     = (const float*)d_in[4];
  const float* b1     = (const float*)d_in[5];
  const float* w2     = (const float*)d_in[6];
  const float* b2     = (const float*)d_in[7];
  const float* g1     = (const float*)d_in[8];
  const float* be1    = (const float*)d_in[9];
  const float* g2     = (const float*)d_in[10];
  const float* be2    = (const float*)d_in[11];
  const float* wh     = (const float*)d_in[12];
  const float* bh     = (const float*)d_in[13];
  float* out = (float*)d_out;

  cudaFuncSetAttribute(kP1, cudaFuncAttributeMaxDynamicSharedMemorySize, SMEM_BYTES);
  cudaFuncSetAttribute(kP2, cudaFuncAttributeMaxDynamicSharedMemorySize, SMEM_BYTES);
  cudaFuncSetAttribute(kP3, cudaFuncAttributeMaxDynamicSharedMemorySize, SMEM_BYTES);
  cudaFuncSetAttribute(kP4, cudaFuncAttributeMaxDynamicSharedMemorySize, SMEM_BYTES);
  cudaFuncSetAttribute(kMeasure, cudaFuncAttributeMaxDynamicSharedMemorySize, SMEM_BYTES);

  kSetup<<<1, 32>>>(ra, trx, try_);
  kNorm<<<BSZ, 256>>>(states);
  kP1<<<BSZ * 4, NTP, SMEM_BYTES>>>(states);
  kP2<<<BSZ * 4, NTP, SMEM_BYTES>>>();
  kP3<<<BSZ * 4, NTP, SMEM_BYTES>>>();
  kP4<<<BSZ * 4, NTP, SMEM_BYTES>>>();
  kMeasure<<<BSZ * 4, NTM, SMEM_BYTES>>>();
  kHead<<<(BSZ + 127) / 128, 128>>>(try_, w1, b1, w2, b2, g1, be1, g2, be2, wh, bh, out);
}